// round 1
// baseline (speedup 1.0000x reference)
#include <cuda_runtime.h>
#include <cuda_bf16.h>
#include <math.h>

// Problem constants (fixed by the reference)
#define BATCH 2
#define DGRID 128
#define DOUT  123          // 128 - 6 + 1
#define KC    6            // composed kernel extent
#define CIN   3
#define COUT  3

// Conv tiling
#define TX 32
#define TY 8
#define TZ 4
#define RX 8               // outputs per thread along x
#define BX 4               // threads in x (BX*RX = TX)
#define NTHREADS (BX*TY*TZ)   // 128

// smem input tile: (TZ+5) x (TY+5) x (TX+5) voxels x 3 ch
#define SZ (TZ+5)          // 9
#define SY (TY+5)          // 13
#define SXV (TX+5)         // 37 voxels
#define SXF (SXV*3)        // 111 floats per (z,y) row
#define SPLANE (SY*SXF)    // 1443
#define SIN_FLOATS (SZ*SPLANE)  // 12987
#define NW (KC*KC*KC*CIN*COUT)  // 1944 composed weights
#define SMEM_FLOATS (SIN_FLOATS + NW)

// ---------------- device scratch (static allocation — allowed) ----------------
__device__ float g_dense[(size_t)BATCH * DGRID * DGRID * DGRID * 3];   // ~50.3 MB
__device__ float g_w12[4*4*4*3*5];   // W1 (*) W2 : 4^3, 3 -> 5
__device__ float g_wc[NW];           // composed 6^3, 3 -> 3; layout [tap][cin][cout]

// ---------------- weight composition ----------------
// W12[k,ci,c5] = sum_{a+b=k} sum_m W1[a,ci,m] * W2[b,m,c5]
__global__ void compose_w12_kernel(const float* __restrict__ W1,
                                   const float* __restrict__ W2) {
    int idx = blockIdx.x * blockDim.x + threadIdx.x;
    if (idx >= 4*4*4*3*5) return;
    int c5 = idx % 5; int t = idx / 5;
    int ci = t % 3;   t /= 3;
    int kx = t % 4;   t /= 4;
    int ky = t % 4;   int kz = t / 4;
    float s = 0.f;
    for (int az = 0; az < 2; az++) {
        int bz = kz - az; if (bz < 0 || bz > 2) continue;
        for (int ay = 0; ay < 2; ay++) {
            int by = ky - ay; if (by < 0 || by > 2) continue;
            for (int ax = 0; ax < 2; ax++) {
                int bx = kx - ax; if (bx < 0 || bx > 2) continue;
                const float* w1 = W1 + (((az*2 + ay)*2 + ax)*3 + ci)*9;
                const float* w2 = W2 + ((bz*3 + by)*3 + bx)*9*5;
                #pragma unroll
                for (int m = 0; m < 9; m++)
                    s += w1[m] * w2[m*5 + c5];
            }
        }
    }
    g_w12[idx] = s;
}

// Wc[k,ci,co] = sum_{d+e=k} sum_c5 W12[d,ci,c5] * W3[e,c5,co]
__global__ void compose_wc_kernel(const float* __restrict__ W3) {
    int idx = blockIdx.x * blockDim.x + threadIdx.x;
    if (idx >= NW) return;
    int co = idx % 3; int t = idx / 3;
    int ci = t % 3;   t /= 3;
    int kx = t % 6;   t /= 6;
    int ky = t % 6;   int kz = t / 6;
    float s = 0.f;
    for (int dz = 0; dz < 4; dz++) {
        int ez = kz - dz; if (ez < 0 || ez > 2) continue;
        for (int dy = 0; dy < 4; dy++) {
            int ey = ky - dy; if (ey < 0 || ey > 2) continue;
            for (int dx = 0; dx < 4; dx++) {
                int ex = kx - dx; if (ex < 0 || ex > 2) continue;
                const float* w12 = g_w12 + (((dz*4 + dy)*4 + dx)*3 + ci)*5;
                const float* w3  = W3 + ((ez*3 + ey)*3 + ex)*5*3;
                #pragma unroll
                for (int c5 = 0; c5 < 5; c5++)
                    s += w12[c5] * w3[c5*3 + co];
            }
        }
    }
    g_wc[idx] = s;
}

// ---------------- scatter ----------------
__global__ void scatter_kernel(const int* __restrict__ coords,
                               const float* __restrict__ voxels, int n) {
    int i = blockIdx.x * blockDim.x + threadIdx.x;
    if (i >= n) return;
    int b = coords[4*i + 0];
    int z = coords[4*i + 1];
    int y = coords[4*i + 2];
    int x = coords[4*i + 3];
    size_t base = ((((size_t)b*DGRID + z)*DGRID + y)*DGRID + x) * 3;
    atomicAdd(&g_dense[base + 0], voxels[3*i + 0]);
    atomicAdd(&g_dense[base + 1], voxels[3*i + 1]);
    atomicAdd(&g_dense[base + 2], voxels[3*i + 2]);
}

// ---------------- fused 6x6x6 conv + bias + relu ----------------
__global__ __launch_bounds__(NTHREADS)
void conv6_kernel(const float* __restrict__ b3, float* __restrict__ out) {
    extern __shared__ float smem[];
    float* sin = smem;                 // SIN_FLOATS
    float* wsm = smem + SIN_FLOATS;    // NW

    const int tid = threadIdx.x + BX*(threadIdx.y + TY*threadIdx.z);

    const int x0 = blockIdx.x * TX;
    const int y0 = blockIdx.y * TY;
    const int zb = blockIdx.z;
    const int NBZ = (DOUT + TZ - 1) / TZ;   // 31
    const int b  = zb / NBZ;
    const int z0 = (zb % NBZ) * TZ;

    // cooperative load: input tile (guarded for grid edge)
    {
        const size_t rowstride = (size_t)DGRID * 3;        // 384
        for (int i = tid; i < SIN_FLOATS; i += NTHREADS) {
            int zz = i / SPLANE;
            int r  = i - zz * SPLANE;
            int yy = r / SXF;
            int xc = r - yy * SXF;       // flat x*3+c within tile
            int gz = z0 + zz;
            int gy = y0 + yy;
            int gxc = x0 * 3 + xc;       // flat x*3+c global
            float v = 0.f;
            if (gz < DGRID && gy < DGRID && gxc < (int)rowstride) {
                v = g_dense[(((size_t)b*DGRID + gz)*DGRID + gy)*rowstride + gxc];
            }
            sin[i] = v;
        }
        for (int i = tid; i < NW; i += NTHREADS) wsm[i] = g_wc[i];
    }
    __syncthreads();

    float acc[RX][COUT];
    #pragma unroll
    for (int j = 0; j < RX; j++)
        #pragma unroll
        for (int c = 0; c < COUT; c++) acc[j][c] = 0.f;

    const int xoff = threadIdx.x * (RX * 3);   // float offset of this thread's x window

    for (int kz = 0; kz < KC; kz++) {
        for (int ky = 0; ky < KC; ky++) {
            const float* rp = &sin[((threadIdx.z + kz)*SY + (threadIdx.y + ky))*SXF + xoff];
            float r[ (RX + 5) * 3 ];           // 39 floats
            #pragma unroll
            for (int v = 0; v < (RX + 5) * 3; v++) r[v] = rp[v];

            const float* wp = &wsm[(kz*KC + ky)*KC*9];
            #pragma unroll
            for (int kx = 0; kx < KC; kx++) {
                float w[9];
                #pragma unroll
                for (int t = 0; t < 9; t++) w[t] = wp[kx*9 + t];
                #pragma unroll
                for (int j = 0; j < RX; j++) {
                    #pragma unroll
                    for (int ci = 0; ci < 3; ci++) {
                        float xv = r[(j + kx)*3 + ci];
                        #pragma unroll
                        for (int co = 0; co < 3; co++)
                            acc[j][co] = fmaf(xv, w[ci*3 + co], acc[j][co]);
                    }
                }
            }
        }
    }

    // epilogue: bias + relu + store
    const float bb0 = b3[0], bb1 = b3[1], bb2 = b3[2];
    const int oz = z0 + threadIdx.z;
    const int oy = y0 + threadIdx.y;
    if (oz < DOUT && oy < DOUT) {
        const int oxb = x0 + threadIdx.x * RX;
        size_t rowbase = (((size_t)b*DOUT + oz)*DOUT + oy) * (size_t)DOUT * 3;
        #pragma unroll
        for (int j = 0; j < RX; j++) {
            int ox = oxb + j;
            if (ox < DOUT) {
                size_t o = rowbase + (size_t)ox * 3;
                out[o + 0] = fmaxf(acc[j][0] + bb0, 0.f);
                out[o + 1] = fmaxf(acc[j][1] + bb1, 0.f);
                out[o + 2] = fmaxf(acc[j][2] + bb2, 0.f);
            }
        }
    }
}

// ---------------- launch ----------------
extern "C" void kernel_launch(void* const* d_in, const int* in_sizes, int n_in,
                              void* d_out, int out_size) {
    const int*   coords = (const int*)  d_in[0];
    const float* voxels = (const float*)d_in[1];
    const float* W1     = (const float*)d_in[2];
    const float* W2     = (const float*)d_in[3];
    const float* W3     = (const float*)d_in[4];
    const float* b3     = (const float*)d_in[5];
    float*       out    = (float*)d_out;

    const int n = in_sizes[0] / 4;

    // compose weights (tiny)
    compose_w12_kernel<<< (4*4*4*3*5 + 255)/256, 256 >>>(W1, W2);
    compose_wc_kernel<<< (NW + 255)/256, 256 >>>(W3);

    // zero the dense grid
    void* densep = nullptr;
    cudaGetSymbolAddress(&densep, g_dense);
    cudaMemsetAsync(densep, 0, (size_t)BATCH*DGRID*DGRID*DGRID*3*sizeof(float));

    // scatter sparse voxels
    scatter_kernel<<< (n + 255)/256, 256 >>>(coords, voxels, n);

    // fused conv
    const size_t smem_bytes = (size_t)SMEM_FLOATS * sizeof(float);
    cudaFuncSetAttribute(conv6_kernel,
                         cudaFuncAttributeMaxDynamicSharedMemorySize,
                         (int)smem_bytes);
    dim3 block(BX, TY, TZ);
    dim3 grid((DOUT + TX - 1)/TX,          // 4
              (DOUT + TY - 1)/TY,          // 16
              BATCH * ((DOUT + TZ - 1)/TZ));  // 62
    conv6_kernel<<<grid, block, smem_bytes>>>(b3, out);
}